// round 13
// baseline (speedup 1.0000x reference)
#include <cuda_runtime.h>
#include <cuda_fp16.h>

// Problem constants
#define B_    2
#define N_    4096
#define DIM_  512
#define H_    8
#define DH_   64
#define BN_   (B_*N_)          // 8192 rows
#define INNER (H_*DH_)         // 512

// ---------------- scratch (device globals; no runtime alloc) ----------------
__device__ __half g_x  [BN_*DIM_];         // x as fp16, [row][k]
__device__ __half g_WT [(3*INNER)*DIM_];   // [c][k]: 0..511 Wq cols, 512..1023 K, 1024..1535 V
__device__ __half g_WoT[DIM_*INNER];       // [n][k]
__device__ __half g_Q  [B_*H_*N_*DH_];     // [b][h][n][d], pre-scaled (1/64)*log2e
__device__ __half g_K  [B_*H_*N_*DH_];
__device__ __half g_V  [B_*H_*N_*DH_];
__device__ __half g_attn[BN_*INNER];       // [b*n][h*DH+d]

// ---------------- helpers ----------------
__device__ __forceinline__ void mmaf16(float* c, unsigned a0, unsigned a1,
                                       unsigned a2, unsigned a3,
                                       unsigned b0, unsigned b1) {
    asm("mma.sync.aligned.m16n8k16.row.col.f32.f16.f16.f32 "
        "{%0,%1,%2,%3}, {%4,%5,%6,%7}, {%8,%9}, {%0,%1,%2,%3};"
        : "+f"(c[0]), "+f"(c[1]), "+f"(c[2]), "+f"(c[3])
        : "r"(a0), "r"(a1), "r"(a2), "r"(a3), "r"(b0), "r"(b1));
}
__device__ __forceinline__ void mmaf16h(unsigned* c, unsigned a0, unsigned a1,
                                        unsigned a2, unsigned a3,
                                        unsigned b0, unsigned b1) {
    asm("mma.sync.aligned.m16n8k16.row.col.f16.f16.f16.f16 "
        "{%0,%1}, {%2,%3,%4,%5}, {%6,%7}, {%0,%1};"
        : "+r"(c[0]), "+r"(c[1])
        : "r"(a0), "r"(a1), "r"(a2), "r"(a3), "r"(b0), "r"(b1));
}
__device__ __forceinline__ void cpa16(void* smem_dst, const void* gsrc) {
    unsigned s = (unsigned)__cvta_generic_to_shared(smem_dst);
    asm volatile("cp.async.cg.shared.global [%0], [%1], 16;" :: "r"(s), "l"(gsrc));
}
__device__ __forceinline__ void cpa_commit() { asm volatile("cp.async.commit_group;"); }
template<int NN> __device__ __forceinline__ void cpa_wait() {
    asm volatile("cp.async.wait_group %0;" :: "n"(NN));
}
__device__ __forceinline__ void ldsm4(unsigned& r0, unsigned& r1,
                                      unsigned& r2, unsigned& r3, unsigned addr) {
    asm volatile("ldmatrix.sync.aligned.m8n8.x4.shared.b16 {%0,%1,%2,%3}, [%4];"
        : "=r"(r0), "=r"(r1), "=r"(r2), "=r"(r3) : "r"(addr));
}
__device__ __forceinline__ void ldsm4t(unsigned& r0, unsigned& r1,
                                       unsigned& r2, unsigned& r3, unsigned addr) {
    asm volatile("ldmatrix.sync.aligned.m8n8.x4.trans.shared.b16 {%0,%1,%2,%3}, [%4];"
        : "=r"(r0), "=r"(r1), "=r"(r2), "=r"(r3) : "r"(addr));
}
__device__ __forceinline__ void ldsm2t(unsigned& r0, unsigned& r1, unsigned addr) {
    asm volatile("ldmatrix.sync.aligned.m8n8.x2.trans.shared.b16 {%0,%1}, [%2];"
        : "=r"(r0), "=r"(r1) : "r"(addr));
}
__device__ __forceinline__ unsigned h2u(__half2 h) { return *(unsigned*)&h; }
__device__ __forceinline__ __half2 u2h(unsigned u) { return *(__half2*)&u; }
__device__ __forceinline__ float ex2f(float x) {
    float r; asm("ex2.approx.f32 %0, %1;" : "=f"(r) : "f"(x)); return r;
}
__device__ __forceinline__ unsigned ex2h2(unsigned x) {
    unsigned r; asm("ex2.approx.f16x2 %0, %1;" : "=r"(r) : "r"(x)); return r;
}

// =====================================================================
// Fused pre-pass: blocks 0..4095 convert x; blocks 4096..5119 transpose W.
// =====================================================================
__global__ void prepass_kernel(const float* __restrict__ x,
                               const float* __restrict__ Wq,
                               const float* __restrict__ Wkv,
                               const float* __restrict__ Wo)
{
    const int bid = blockIdx.x, tid = threadIdx.x;
    if (bid < 4096) {
        int i = bid * 256 + tid;
        float4 v = ((const float4*)x)[i];
        uint2 o;
        o.x = h2u(__floats2half2_rn(v.x, v.y));
        o.y = h2u(__floats2half2_rn(v.z, v.w));
        ((uint2*)g_x)[i] = o;
    } else {
        __shared__ float s[32][33];
        int tb = bid - 4096;
        int bx = tb & 63, by = tb >> 6;
        const float* src; int ldsrc, cg; __half* dst;
        if (bx < 16)      { src = Wq;  ldsrc = 512;  cg = bx;      dst = g_WT; }
        else if (bx < 48) { src = Wkv; ldsrc = 1024; cg = bx - 16; dst = g_WT + (size_t)512*DIM_; }
        else              { src = Wo;  ldsrc = 512;  cg = bx - 48; dst = g_WoT; }
        int c0 = cg * 32, k0 = by * 32;
        int tx = tid & 31, ty = tid >> 5;
        #pragma unroll
        for (int i = 0; i < 32; i += 8)
            s[ty + i][tx] = src[(size_t)(k0 + ty + i) * ldsrc + c0 + tx];
        __syncthreads();
        #pragma unroll
        for (int i = 0; i < 32; i += 8)
            dst[(size_t)(c0 + ty + i) * 512 + k0 + tx] = __float2half_rn(s[tx][ty + i]);
    }
}

// =====================================================================
// fp16 GEMM core — single-sync pipelined loop (round-11 LDS fragments)
// =====================================================================
#define GS 20
#define GTILE (128*GS)

__device__ __forceinline__ void gemm_stage(const __half* __restrict__ A,
                                           const __half* __restrict__ W,
                                           int row0, int bcol0, int k0,
                                           unsigned* As, unsigned* Bs, int tid)
{
    #pragma unroll
    for (int i = 0; i < 2; i++) {
        int idx = tid + i*256;
        int r = idx >> 2, seg = idx & 3;
        cpa16(&As[r*GS + seg*4], &A[(size_t)(row0  + r)*512 + k0 + seg*8]);
        cpa16(&Bs[r*GS + seg*4], &W[(size_t)(bcol0 + r)*512 + k0 + seg*8]);
    }
}

__device__ __forceinline__ void gemm_f16(const __half* __restrict__ A,
                                         const __half* __restrict__ W,
                                         int row0, int bcol0,
                                         float (&acc)[4][4][4],
                                         unsigned* AsBuf, unsigned* BsBuf)
{
    const int tid  = threadIdx.x;
    const int lane = tid & 31, w = tid >> 5;
    const int gid  = lane >> 2, tig = lane & 3;
    const int m0w  = (w >> 2) * 64;
    const int n0w  = (w & 3) * 32;

    #pragma unroll
    for (int mt = 0; mt < 4; mt++)
        #pragma unroll
        for (int nt = 0; nt < 4; nt++)
            #pragma unroll
            for (int r = 0; r < 4; r++) acc[mt][nt][r] = 0.0f;

    gemm_stage(A, W, row0, bcol0, 0, AsBuf, BsBuf, tid);
    cpa_commit();

    for (int it = 0; it < 16; it++) {
        const int buf = it & 1;
        cpa_wait<0>();
        __syncthreads();
        if (it + 1 < 16) {
            gemm_stage(A, W, row0, bcol0, (it+1)*32,
                       AsBuf + (buf^1)*GTILE, BsBuf + (buf^1)*GTILE, tid);
            cpa_commit();
        }

        const unsigned* As = AsBuf + buf*GTILE;
        const unsigned* Bs = BsBuf + buf*GTILE;
        #pragma unroll
        for (int kc = 0; kc < 2; kc++) {
            const int kk = kc * 8;
            unsigned am[4][4];
            #pragma unroll
            for (int mt = 0; mt < 4; mt++) {
                int mr = m0w + mt*16;
                am[mt][0] = As[(mr+gid  )*GS + kk + tig    ];
                am[mt][1] = As[(mr+gid+8)*GS + kk + tig    ];
                am[mt][2] = As[(mr+gid  )*GS + kk + tig + 4];
                am[mt][3] = As[(mr+gid+8)*GS + kk + tig + 4];
            }
            unsigned bn[4][2];
            #pragma unroll
            for (int nt = 0; nt < 4; nt++) {
                bn[nt][0] = Bs[(n0w+nt*8+gid)*GS + kk + tig    ];
                bn[nt][1] = Bs[(n0w+nt*8+gid)*GS + kk + tig + 4];
            }
            #pragma unroll
            for (int mt = 0; mt < 4; mt++)
                #pragma unroll
                for (int nt = 0; nt < 4; nt++)
                    mmaf16(acc[mt][nt], am[mt][0], am[mt][1], am[mt][2], am[mt][3],
                           bn[nt][0], bn[nt][1]);
        }
    }
}

// ---- Kernel 1: QKV projection ----
#define QSCALE (1.44269504088896f / 64.0f)

__global__ __launch_bounds__(256, 2) void qkv_f16_kernel()
{
    __shared__ unsigned As[2*GTILE];
    __shared__ unsigned Bs[2*GTILE];

    const int bx = blockIdx.x;
    const int row0 = blockIdx.y * 128;
    const int which = bx >> 2;
    const int bcol0 = bx * 128;
    const int lcolbase = (bx & 3) * 128;

    float acc[4][4][4];
    gemm_f16(g_x, g_WT, row0, bcol0, acc, As, Bs);

    const float scale = (which == 0) ? QSCALE : 1.0f;
    __half* dst = (which == 0) ? g_Q : (which == 1 ? g_K : g_V);

    const int lane = threadIdx.x & 31, w = threadIdx.x >> 5;
    const int gid = lane >> 2, tig = lane & 3;
    const int m0w = (w >> 2) * 64, n0w = (w & 3) * 32;

    #pragma unroll
    for (int mt = 0; mt < 4; mt++) {
        int r0 = row0 + m0w + mt*16 + gid;
        int r1 = r0 + 8;
        int b0i = r0 >> 12, n0i = r0 & (N_-1);
        int b1i = r1 >> 12, n1i = r1 & (N_-1);
        #pragma unroll
        for (int nt = 0; nt < 4; nt++) {
            int c = lcolbase + n0w + nt*8 + 2*tig;
            int h = c >> 6, d = c & 63;
            __half2 v0 = __floats2half2_rn(acc[mt][nt][0]*scale, acc[mt][nt][1]*scale);
            __half2 v1 = __floats2half2_rn(acc[mt][nt][2]*scale, acc[mt][nt][3]*scale);
            *(__half2*)&dst[(((size_t)(b0i*H_ + h)*N_ + n0i)*DH_ + d)] = v0;
            *(__half2*)&dst[(((size_t)(b1i*H_ + h)*N_ + n1i)*DH_ + d)] = v1;
        }
    }
}

// ---- Kernel 3: out = g_attn @ WoT^T + bo ----
__global__ __launch_bounds__(256, 2) void out_f16_kernel(
    const float* __restrict__ bo, float* __restrict__ out)
{
    __shared__ unsigned As[2*GTILE];
    __shared__ unsigned Bs[2*GTILE];

    const int row0 = blockIdx.y * 128;
    const int wcol = blockIdx.x * 128;

    float acc[4][4][4];
    gemm_f16(g_attn, g_WoT, row0, wcol, acc, As, Bs);

    const int lane = threadIdx.x & 31, w = threadIdx.x >> 5;
    const int gid = lane >> 2, tig = lane & 3;
    const int m0w = (w >> 2) * 64, n0w = (w & 3) * 32;

    #pragma unroll
    for (int mt = 0; mt < 4; mt++) {
        int r0 = row0 + m0w + mt*16 + gid;
        int r1 = r0 + 8;
        #pragma unroll
        for (int nt = 0; nt < 4; nt++) {
            int c = wcol + n0w + nt*8 + 2*tig;
            float2 bias = *(const float2*)&bo[c];
            float2 v0 = make_float2(acc[mt][nt][0] + bias.x, acc[mt][nt][1] + bias.y);
            float2 v1 = make_float2(acc[mt][nt][2] + bias.x, acc[mt][nt][3] + bias.y);
            *(float2*)&out[(size_t)r0*512 + c] = v0;
            *(float2*)&out[(size_t)r1*512 + c] = v1;
        }
    }
}

// =====================================================================
// Kernel 2: causal flash attention — paired tiles, Q frags from gmem,
//   packed fp16 running max, one sync per key-tile, no half-boundary sync.
// =====================================================================
#define FS 36               // half2 stride per row (32 used + 4 pad)
#define KVT (64*FS)

__global__ __launch_bounds__(256, 2) void flash_f16_kernel()
{
    __shared__ unsigned SMEM[4*KVT];    // K0 K1 V0 V1
    unsigned* Ks = SMEM;
    unsigned* Vs = SMEM + 2*KVT;

    const int bh = blockIdx.y, b = bh >> 3, h = bh & 7;
    const int tid = threadIdx.x, lane = tid & 31, w = tid >> 5;
    const int gid = lane >> 2, tig = lane & 3;

    const __half* Qb = g_Q + (size_t)bh * N_ * DH_;
    const __half* Kb = g_K + (size_t)bh * N_ * DH_;
    const __half* Vb = g_V + (size_t)bh * N_ * DH_;

    // ---- init V ones-column padding (cols 64..71; staging writes 0..63) ----
    if (tid < 128) {
        int rr = tid & 63, bu = tid >> 6;
        unsigned* vp = Vs + bu*KVT + rr*FS + 32;
        vp[0] = 0x00003C00u;   // (1.0h, 0.0h)
        vp[1] = 0u; vp[2] = 0u; vp[3] = 0u;
    }

    for (int half = 0; half < 2; half++) {
        const int tile = half ? (31 - (int)blockIdx.x) : (int)blockIdx.x;
        const int qrow0 = tile * 128;
        const int nkt = (qrow0 + 128) / 64;     // even, >= 2

        // ---- stage first K/V tile (cross-half smem reuse is ordered by the
        //      kt=0 block barrier; slot usage verified: last-read slots are 1) ----
        #pragma unroll
        for (int i = 0; i < 2; i++) {
            int idx = tid + i*256;
            int rr = idx >> 3, seg = idx & 7;
            cpa16(&Ks[rr*FS + seg*4], &Kb[(size_t)rr*DH_ + seg*8]);
            cpa16(&Vs[rr*FS + seg*4], &Vb[(size_t)rr*DH_ + seg*8]);
        }
        cpa_commit();

        // ---- Q fragments directly from gmem (latency hides under cp.async) ----
        unsigned aq[4][4];
        {
            const __half* Qr = Qb + (size_t)(qrow0 + 16*w + gid) * DH_;
            #pragma unroll
            for (int c = 0; c < 4; c++) {
                aq[c][0] = *(const unsigned*)(Qr + 16*c + 2*tig);
                aq[c][1] = *(const unsigned*)(Qr + 8*DH_ + 16*c + 2*tig);
                aq[c][2] = *(const unsigned*)(Qr + 16*c + 2*tig + 8);
                aq[c][3] = *(const unsigned*)(Qr + 8*DH_ + 16*c + 2*tig + 8);
            }
        }

        float oc[8][4];
        #pragma unroll
        for (int jd = 0; jd < 8; jd++)
            #pragma unroll
            for (int r = 0; r < 4; r++) oc[jd][r] = 0.0f;
        float cl0 = 0.0f, cl1 = 0.0f, cl2 = 0.0f, cl3 = 0.0f;
        unsigned m_pk = 0xFC00FC00u;            // packed (-inf, -inf) = (m_r, m_r8)
        const int wrow_min = qrow0 + 16*w;
        const int row_r = wrow_min + gid, row_r8 = row_r + 8;
        const int lrow = lane & 15;
        const int lcol8 = (lane & 16) ? 8 : 0;

        for (int kt = 0; kt < nkt; kt++) {
            const int k0 = kt * 64;
            const int buf = kt & 1;
            cpa_wait<0>();
            __syncthreads();
            if (kt + 1 < nkt) {
                const int kn = k0 + 64;
                unsigned* Kd = Ks + (buf^1)*KVT;
                unsigned* Vd = Vs + (buf^1)*KVT;
                #pragma unroll
                for (int i = 0; i < 2; i++) {
                    int idx = tid + i*256;
                    int rr = idx >> 3, seg = idx & 7;
                    cpa16(&Kd[rr*FS + seg*4], &Kb[(size_t)(kn+rr)*DH_ + seg*8]);
                    cpa16(&Vd[rr*FS + seg*4], &Vb[(size_t)(kn+rr)*DH_ + seg*8]);
                }
                cpa_commit();
            }

            const bool active = (k0 <= wrow_min + 15);
            if (active) {
                const unsigned* Kbuf = Ks + buf*KVT;
                const unsigned* Vbuf = Vs + buf*KVT;

                // ---- S = Q K^T (fp16 accumulators; non-trans ldsm for K) ----
                unsigned sh[8], sh8[8];
                #pragma unroll
                for (int j = 0; j < 8; j++) {
                    unsigned sc2[2] = {0u, 0u};
                    unsigned kA[4], kB[4];
                    unsigned base = (unsigned)__cvta_generic_to_shared(
                        Kbuf + (j*8 + (lane & 7))*FS + ((lane >> 3) & 3)*4);
                    ldsm4(kA[0], kA[1], kA[2], kA[3], base);
                    ldsm4(kB[0], kB[1], kB[2], kB[3], base + 64);
                    mmaf16h(sc2, aq[0][0], aq[0][1], aq[0][2], aq[0][3], kA[0], kA[1]);
                    mmaf16h(sc2, aq[1][0], aq[1][1], aq[1][2], aq[1][3], kA[2], kA[3]);
                    mmaf16h(sc2, aq[2][0], aq[2][1], aq[2][2], aq[2][3], kB[0], kB[1]);
                    mmaf16h(sc2, aq[3][0], aq[3][1], aq[3][2], aq[3][3], kB[2], kB[3]);
                    sh[j] = sc2[0]; sh8[j] = sc2[1];
                }
                // ---- causal mask ----
                if (k0 + 63 > wrow_min) {
                    #pragma unroll
                    for (int j = 0; j < 8; j++) {
                        int c0 = k0 + j*8 + 2*tig;
                        unsigned mk  = (c0 > row_r  ? 0xFC00u : 0u) | (c0+1 > row_r  ? 0xFC000000u : 0u);
                        unsigned mk8 = (c0 > row_r8 ? 0xFC00u : 0u) | (c0+1 > row_r8 ? 0xFC000000u : 0u);
                        sh[j]  = h2u(__hadd2(u2h(sh[j]),  u2h(mk)));
                        sh8[j] = h2u(__hadd2(u2h(sh8[j]), u2h(mk8)));
                    }
                }
                // ---- packed max: (m_r, m_r8) in one half2 ----
                __half2 a2 = u2h(sh[0]), b2 = u2h(sh8[0]);
                #pragma unroll
                for (int j = 1; j < 8; j++) {
                    a2 = __hmax2(a2, u2h(sh[j]));
                    b2 = __hmax2(b2, u2h(sh8[j]));
                }
                __half2 mx = __halves2half2(
                    __hmax(__low2half(a2), __high2half(a2)),
                    __hmax(__low2half(b2), __high2half(b2)));
                mx = __hmax2(mx, u2h(__shfl_xor_sync(0xffffffffu, h2u(mx), 1)));
                mx = __hmax2(mx, u2h(__shfl_xor_sync(0xffffffffu, h2u(mx), 2)));
                __half2 mnew = __hmax2(u2h(m_pk), mx);
                float corr_r  = ex2f(__low2float(u2h(m_pk))  - __low2float(mnew));
                float corr_r8 = ex2f(__high2float(u2h(m_pk)) - __high2float(mnew));
                m_pk = h2u(mnew);
                __half2 m2r  = __half2half2(__low2half(mnew));
                __half2 m2r8 = __half2half2(__high2half(mnew));

                // ---- p = ex2(s - m) in place -> PV A-fragments ----
                #pragma unroll
                for (int j = 0; j < 8; j++) {
                    sh[j]  = ex2h2(h2u(__hsub2(u2h(sh[j]),  m2r )));
                    sh8[j] = ex2h2(h2u(__hsub2(u2h(sh8[j]), m2r8)));
                }

                // ---- rescale accumulators ----
                #pragma unroll
                for (int jd = 0; jd < 8; jd++) {
                    oc[jd][0] *= corr_r;  oc[jd][1] *= corr_r;
                    oc[jd][2] *= corr_r8; oc[jd][3] *= corr_r8;
                }
                cl0 *= corr_r; cl2 *= corr_r8;

                // ---- O += P V ; l += P 1 ----
                #pragma unroll
                for (int c = 0; c < 4; c++) {
                    #pragma unroll
                    for (int jd2 = 0; jd2 < 4; jd2++) {
                        unsigned addr = (unsigned)__cvta_generic_to_shared(
                            (const char*)(Vbuf + (c*16 + lrow)*FS + jd2*8) + lcol8*2);
                        unsigned r0, r1, r2, r3;
                        ldsm4t(r0, r1, r2, r3, addr);
                        mmaf16(oc[2*jd2    ], sh[2*c], sh8[2*c], sh[2*c+1], sh8[2*c+1], r0, r1);
                        mmaf16(oc[2*jd2 + 1], sh[2*c], sh8[2*c], sh[2*c+1], sh8[2*c+1], r2, r3);
                    }
                    unsigned laddr = (unsigned)__cvta_generic_to_shared(
                        Vbuf + (c*16 + lrow)*FS + 32);
                    unsigned l0, l1;
                    ldsm2t(l0, l1, laddr);
                    float clf[4] = {cl0, cl1, cl2, cl3};
                    mmaf16(clf, sh[2*c], sh8[2*c], sh[2*c+1], sh8[2*c+1], l0, l1);
                    cl0 = clf[0]; cl1 = clf[1]; cl2 = clf[2]; cl3 = clf[3];
                }
            }
        }

        // ---- epilogue: l in col 64 (tig==0 lanes); broadcast in quad ----
        float l_r  = __shfl_sync(0xffffffffu, cl0, lane & ~3);
        float l_r8 = __shfl_sync(0xffffffffu, cl2, lane & ~3);
        float inv_r = 1.0f / l_r, inv_r8 = 1.0f / l_r8;
        __half* o0 = g_attn + ((size_t)(b*N_ + row_r )*INNER + h*DH_);
        __half* o1 = g_attn + ((size_t)(b*N_ + row_r8)*INNER + h*DH_);
        #pragma unroll
        for (int jd = 0; jd < 8; jd++) {
            int c = jd*8 + 2*tig;
            *(__half2*)&o0[c] = __floats2half2_rn(oc[jd][0]*inv_r,  oc[jd][1]*inv_r );
            *(__half2*)&o1[c] = __floats2half2_rn(oc[jd][2]*inv_r8, oc[jd][3]*inv_r8);
        }
    }
}

// =====================================================================
extern "C" void kernel_launch(void* const* d_in, const int* in_sizes, int n_in,
                              void* d_out, int out_size)
{
    const float* x   = (const float*)d_in[0];
    const float* Wq  = (const float*)d_in[1];
    const float* Wkv = (const float*)d_in[2];
    const float* Wo  = (const float*)d_in[3];
    const float* bo  = (const float*)d_in[4];
    float* out = (float*)d_out;

    prepass_kernel<<<4096 + 1024, 256>>>(x, Wq, Wkv, Wo);
    qkv_f16_kernel<<<dim3(12, 64), 256>>>();
    flash_f16_kernel<<<dim3(16, B_*H_), 256>>>();
    out_f16_kernel<<<dim3(4, 64), 256>>>(bo, out);
}

// round 15
// speedup vs baseline: 1.0291x; 1.0291x over previous
#include <cuda_runtime.h>
#include <cuda_fp16.h>

// Problem constants
#define B_    2
#define N_    4096
#define DIM_  512
#define H_    8
#define DH_   64
#define BN_   (B_*N_)          // 8192 rows
#define INNER (H_*DH_)         // 512

// ---------------- scratch (device globals; no runtime alloc) ----------------
__device__ __half g_x  [BN_*DIM_];         // x as fp16, [row][k]
__device__ __half g_WT [(3*INNER)*DIM_];   // [c][k]: 0..511 Wq cols, 512..1023 K, 1024..1535 V
__device__ __half g_WoT[DIM_*INNER];       // [n][k]
__device__ __half g_Q  [B_*H_*N_*DH_];     // [b][h][n][d], pre-scaled (1/64)*log2e
__device__ __half g_K  [B_*H_*N_*DH_];
__device__ __half g_V  [B_*H_*N_*DH_];
__device__ __half g_attn[BN_*INNER];       // [b*n][h*DH+d]

// ---------------- helpers ----------------
__device__ __forceinline__ void mmaf16(float* c, unsigned a0, unsigned a1,
                                       unsigned a2, unsigned a3,
                                       unsigned b0, unsigned b1) {
    asm("mma.sync.aligned.m16n8k16.row.col.f32.f16.f16.f32 "
        "{%0,%1,%2,%3}, {%4,%5,%6,%7}, {%8,%9}, {%0,%1,%2,%3};"
        : "+f"(c[0]), "+f"(c[1]), "+f"(c[2]), "+f"(c[3])
        : "r"(a0), "r"(a1), "r"(a2), "r"(a3), "r"(b0), "r"(b1));
}
__device__ __forceinline__ void mmaf16h(unsigned* c, unsigned a0, unsigned a1,
                                        unsigned a2, unsigned a3,
                                        unsigned b0, unsigned b1) {
    asm("mma.sync.aligned.m16n8k16.row.col.f16.f16.f16.f16 "
        "{%0,%1}, {%2,%3,%4,%5}, {%6,%7}, {%0,%1};"
        : "+r"(c[0]), "+r"(c[1])
        : "r"(a0), "r"(a1), "r"(a2), "r"(a3), "r"(b0), "r"(b1));
}
__device__ __forceinline__ void cpa16(void* smem_dst, const void* gsrc) {
    unsigned s = (unsigned)__cvta_generic_to_shared(smem_dst);
    asm volatile("cp.async.cg.shared.global [%0], [%1], 16;" :: "r"(s), "l"(gsrc));
}
__device__ __forceinline__ void cpa_commit() { asm volatile("cp.async.commit_group;"); }
template<int NN> __device__ __forceinline__ void cpa_wait() {
    asm volatile("cp.async.wait_group %0;" :: "n"(NN));
}
__device__ __forceinline__ void ldsm4(unsigned& r0, unsigned& r1,
                                      unsigned& r2, unsigned& r3, unsigned addr) {
    asm volatile("ldmatrix.sync.aligned.m8n8.x4.shared.b16 {%0,%1,%2,%3}, [%4];"
        : "=r"(r0), "=r"(r1), "=r"(r2), "=r"(r3) : "r"(addr));
}
__device__ __forceinline__ void ldsm4t(unsigned& r0, unsigned& r1,
                                       unsigned& r2, unsigned& r3, unsigned addr) {
    asm volatile("ldmatrix.sync.aligned.m8n8.x4.trans.shared.b16 {%0,%1,%2,%3}, [%4];"
        : "=r"(r0), "=r"(r1), "=r"(r2), "=r"(r3) : "r"(addr));
}
__device__ __forceinline__ void ldsm2t(unsigned& r0, unsigned& r1, unsigned addr) {
    asm volatile("ldmatrix.sync.aligned.m8n8.x2.trans.shared.b16 {%0,%1}, [%2];"
        : "=r"(r0), "=r"(r1) : "r"(addr));
}
__device__ __forceinline__ unsigned h2u(__half2 h) { return *(unsigned*)&h; }
__device__ __forceinline__ __half2 u2h(unsigned u) { return *(__half2*)&u; }
__device__ __forceinline__ float ex2f(float x) {
    float r; asm("ex2.approx.f32 %0, %1;" : "=f"(r) : "f"(x)); return r;
}
__device__ __forceinline__ unsigned ex2h2(unsigned x) {
    unsigned r; asm("ex2.approx.f16x2 %0, %1;" : "=r"(r) : "r"(x)); return r;
}

// =====================================================================
// Fused pre-pass: blocks 0..4095 convert x; blocks 4096..5119 transpose W.
// =====================================================================
__global__ void prepass_kernel(const float* __restrict__ x,
                               const float* __restrict__ Wq,
                               const float* __restrict__ Wkv,
                               const float* __restrict__ Wo)
{
    const int bid = blockIdx.x, tid = threadIdx.x;
    if (bid < 4096) {
        int i = bid * 256 + tid;
        float4 v = ((const float4*)x)[i];
        uint2 o;
        o.x = h2u(__floats2half2_rn(v.x, v.y));
        o.y = h2u(__floats2half2_rn(v.z, v.w));
        ((uint2*)g_x)[i] = o;
    } else {
        __shared__ float s[32][33];
        int tb = bid - 4096;
        int bx = tb & 63, by = tb >> 6;
        const float* src; int ldsrc, cg; __half* dst;
        if (bx < 16)      { src = Wq;  ldsrc = 512;  cg = bx;      dst = g_WT; }
        else if (bx < 48) { src = Wkv; ldsrc = 1024; cg = bx - 16; dst = g_WT + (size_t)512*DIM_; }
        else              { src = Wo;  ldsrc = 512;  cg = bx - 48; dst = g_WoT; }
        int c0 = cg * 32, k0 = by * 32;
        int tx = tid & 31, ty = tid >> 5;
        #pragma unroll
        for (int i = 0; i < 32; i += 8)
            s[ty + i][tx] = src[(size_t)(k0 + ty + i) * ldsrc + c0 + tx];
        __syncthreads();
        #pragma unroll
        for (int i = 0; i < 32; i += 8)
            dst[(size_t)(c0 + ty + i) * 512 + k0 + tx] = __float2half_rn(s[tx][ty + i]);
    }
}

// =====================================================================
// fp16 GEMM core — 3-stage cp.async pipeline (chunk = 32 halves of K).
// Dynamic smem: As = dyn[0..3*GTILE), Bs = dyn[3*GTILE..6*GTILE).
// =====================================================================
#define GS 20
#define GTILE (128*GS)
#define GEMM_SMEM (6*GTILE*4)   // 61440 bytes

__device__ __forceinline__ void gemm_stage(const __half* __restrict__ A,
                                           const __half* __restrict__ W,
                                           int row0, int bcol0, int k0,
                                           unsigned* As, unsigned* Bs, int tid)
{
    #pragma unroll
    for (int i = 0; i < 2; i++) {
        int idx = tid + i*256;
        int r = idx >> 2, seg = idx & 3;
        cpa16(&As[r*GS + seg*4], &A[(size_t)(row0  + r)*512 + k0 + seg*8]);
        cpa16(&Bs[r*GS + seg*4], &W[(size_t)(bcol0 + r)*512 + k0 + seg*8]);
    }
}

__device__ __forceinline__ void gemm_f16(const __half* __restrict__ A,
                                         const __half* __restrict__ W,
                                         int row0, int bcol0,
                                         float (&acc)[4][4][4],
                                         unsigned* AsBuf, unsigned* BsBuf)
{
    const int tid  = threadIdx.x;
    const int lane = tid & 31, w = tid >> 5;
    const int gid  = lane >> 2, tig = lane & 3;
    const int m0w  = (w >> 2) * 64;
    const int n0w  = (w & 3) * 32;

    #pragma unroll
    for (int mt = 0; mt < 4; mt++)
        #pragma unroll
        for (int nt = 0; nt < 4; nt++)
            #pragma unroll
            for (int r = 0; r < 4; r++) acc[mt][nt][r] = 0.0f;

    // prologue: stage chunks 0 (k=0) and 1 (k=32)
    gemm_stage(A, W, row0, bcol0, 0,  AsBuf,         BsBuf,         tid);
    cpa_commit();
    gemm_stage(A, W, row0, bcol0, 32, AsBuf + GTILE, BsBuf + GTILE, tid);
    cpa_commit();

    for (int it = 0; it < 16; it++) {
        const int buf = it % 3;
        if (it + 2 < 16) {
            cpa_wait<1>();          // chunk it landed; chunk it+1 may be in flight
            __syncthreads();
            const int sb = (it + 2) % 3;
            gemm_stage(A, W, row0, bcol0, (it + 2) * 32,
                       AsBuf + sb*GTILE, BsBuf + sb*GTILE, tid);
            cpa_commit();
        } else {
            cpa_wait<0>();
            __syncthreads();
        }

        const unsigned* As = AsBuf + buf*GTILE;
        const unsigned* Bs = BsBuf + buf*GTILE;
        #pragma unroll
        for (int kc = 0; kc < 2; kc++) {
            const int kk = kc * 8;
            unsigned am[4][4];
            #pragma unroll
            for (int mt = 0; mt < 4; mt++) {
                int mr = m0w + mt*16;
                am[mt][0] = As[(mr+gid  )*GS + kk + tig    ];
                am[mt][1] = As[(mr+gid+8)*GS + kk + tig    ];
                am[mt][2] = As[(mr+gid  )*GS + kk + tig + 4];
                am[mt][3] = As[(mr+gid+8)*GS + kk + tig + 4];
            }
            unsigned bn[4][2];
            #pragma unroll
            for (int nt = 0; nt < 4; nt++) {
                bn[nt][0] = Bs[(n0w+nt*8+gid)*GS + kk + tig    ];
                bn[nt][1] = Bs[(n0w+nt*8+gid)*GS + kk + tig + 4];
            }
            #pragma unroll
            for (int mt = 0; mt < 4; mt++)
                #pragma unroll
                for (int nt = 0; nt < 4; nt++)
                    mmaf16(acc[mt][nt], am[mt][0], am[mt][1], am[mt][2], am[mt][3],
                           bn[nt][0], bn[nt][1]);
        }
    }
}

// ---- Kernel 1: QKV projection ----
#define QSCALE (1.44269504088896f / 64.0f)

__global__ __launch_bounds__(256, 2) void qkv_f16_kernel()
{
    extern __shared__ unsigned dynsmem[];
    unsigned* As = dynsmem;
    unsigned* Bs = dynsmem + 3*GTILE;

    const int bx = blockIdx.x;
    const int row0 = blockIdx.y * 128;
    const int which = bx >> 2;
    const int bcol0 = bx * 128;
    const int lcolbase = (bx & 3) * 128;

    float acc[4][4][4];
    gemm_f16(g_x, g_WT, row0, bcol0, acc, As, Bs);

    const float scale = (which == 0) ? QSCALE : 1.0f;
    __half* dst = (which == 0) ? g_Q : (which == 1 ? g_K : g_V);

    const int lane = threadIdx.x & 31, w = threadIdx.x >> 5;
    const int gid = lane >> 2, tig = lane & 3;
    const int m0w = (w >> 2) * 64, n0w = (w & 3) * 32;

    #pragma unroll
    for (int mt = 0; mt < 4; mt++) {
        int r0 = row0 + m0w + mt*16 + gid;
        int r1 = r0 + 8;
        int b0i = r0 >> 12, n0i = r0 & (N_-1);
        int b1i = r1 >> 12, n1i = r1 & (N_-1);
        #pragma unroll
        for (int nt = 0; nt < 4; nt++) {
            int c = lcolbase + n0w + nt*8 + 2*tig;
            int h = c >> 6, d = c & 63;
            __half2 v0 = __floats2half2_rn(acc[mt][nt][0]*scale, acc[mt][nt][1]*scale);
            __half2 v1 = __floats2half2_rn(acc[mt][nt][2]*scale, acc[mt][nt][3]*scale);
            *(__half2*)&dst[(((size_t)(b0i*H_ + h)*N_ + n0i)*DH_ + d)] = v0;
            *(__half2*)&dst[(((size_t)(b1i*H_ + h)*N_ + n1i)*DH_ + d)] = v1;
        }
    }
}

// ---- Kernel 3: out = g_attn @ WoT^T + bo ----
__global__ __launch_bounds__(256, 2) void out_f16_kernel(
    const float* __restrict__ bo, float* __restrict__ out)
{
    extern __shared__ unsigned dynsmem[];
    unsigned* As = dynsmem;
    unsigned* Bs = dynsmem + 3*GTILE;

    const int row0 = blockIdx.y * 128;
    const int wcol = blockIdx.x * 128;

    float acc[4][4][4];
    gemm_f16(g_attn, g_WoT, row0, wcol, acc, As, Bs);

    const int lane = threadIdx.x & 31, w = threadIdx.x >> 5;
    const int gid = lane >> 2, tig = lane & 3;
    const int m0w = (w >> 2) * 64, n0w = (w & 3) * 32;

    #pragma unroll
    for (int mt = 0; mt < 4; mt++) {
        int r0 = row0 + m0w + mt*16 + gid;
        int r1 = r0 + 8;
        #pragma unroll
        for (int nt = 0; nt < 4; nt++) {
            int c = wcol + n0w + nt*8 + 2*tig;
            float2 bias = *(const float2*)&bo[c];
            float2 v0 = make_float2(acc[mt][nt][0] + bias.x, acc[mt][nt][1] + bias.y);
            float2 v1 = make_float2(acc[mt][nt][2] + bias.x, acc[mt][nt][3] + bias.y);
            *(float2*)&out[(size_t)r0*512 + c] = v0;
            *(float2*)&out[(size_t)r1*512 + c] = v1;
        }
    }
}

// =====================================================================
// Kernel 2: causal flash attention — round-11 winner, unchanged.
// =====================================================================
#define FS 36               // half2 stride per row (32 used + 4 pad)
#define KVT (64*FS)

__global__ __launch_bounds__(256, 2) void flash_f16_kernel()
{
    __shared__ unsigned SMEM[4*KVT];    // [K0 K1 V0 V1]; Q staged over K region
    unsigned* Ks = SMEM;
    unsigned* Vs = SMEM + 2*KVT;

    const int bh = blockIdx.y, b = bh >> 3, h = bh & 7;
    const int tid = threadIdx.x, lane = tid & 31, w = tid >> 5;
    const int gid = lane >> 2, tig = lane & 3;

    const __half* Qb = g_Q + (size_t)bh * N_ * DH_;
    const __half* Kb = g_K + (size_t)bh * N_ * DH_;
    const __half* Vb = g_V + (size_t)bh * N_ * DH_;

    // ---- init V ones-column padding once (cols 64..71; staging writes 0..63) ----
    if (tid < 128) {
        int rr = tid & 63, bu = tid >> 6;
        unsigned* vp = Vs + bu*KVT + rr*FS + 32;
        vp[0] = 0x00003C00u;   // (1.0h, 0.0h)
        vp[1] = 0u; vp[2] = 0u; vp[3] = 0u;
    }

    for (int half = 0; half < 2; half++) {
        const int tile = half ? (31 - (int)blockIdx.x) : (int)blockIdx.x;
        const int qrow0 = tile * 128;

        __syncthreads();   // prior compute done before Q staging reuses K region
        #pragma unroll
        for (int i = 0; i < 4; i++) {
            int idx = tid + i*256;
            int rr = idx >> 3, seg = idx & 7;
            cpa16(&SMEM[rr*FS + seg*4], &Qb[(size_t)(qrow0+rr)*DH_ + seg*8]);
        }
        cpa_commit(); cpa_wait<0>();
        __syncthreads();
        unsigned aq[4][4];
        {
            const unsigned* Qw = SMEM + (16*w)*FS;
            #pragma unroll
            for (int c = 0; c < 4; c++) {
                aq[c][0] = Qw[(gid  )*FS + c*8 + tig    ];
                aq[c][1] = Qw[(gid+8)*FS + c*8 + tig    ];
                aq[c][2] = Qw[(gid  )*FS + c*8 + tig + 4];
                aq[c][3] = Qw[(gid+8)*FS + c*8 + tig + 4];
            }
        }
        __syncthreads();   // Q reads done before K staging overwrites

        float oc[8][4];
        #pragma unroll
        for (int jd = 0; jd < 8; jd++)
            #pragma unroll
            for (int r = 0; r < 4; r++) oc[jd][r] = 0.0f;
        float cl0 = 0.0f, cl1 = 0.0f, cl2 = 0.0f, cl3 = 0.0f;
        float m_r = -1e30f, m_r8 = -1e30f;
        const int wrow_min = qrow0 + 16*w;
        const int row_r = wrow_min + gid, row_r8 = row_r + 8;

        const int nkt = (qrow0 + 128) / 64;

        // stage first K/V tile
        #pragma unroll
        for (int i = 0; i < 2; i++) {
            int idx = tid + i*256;
            int rr = idx >> 3, seg = idx & 7;
            cpa16(&Ks[rr*FS + seg*4], &Kb[(size_t)rr*DH_ + seg*8]);
            cpa16(&Vs[rr*FS + seg*4], &Vb[(size_t)rr*DH_ + seg*8]);
        }
        cpa_commit();

        for (int kt = 0; kt < nkt; kt++) {
            const int k0 = kt * 64;
            const int buf = kt & 1;
            cpa_wait<0>();
            __syncthreads();
            if (kt + 1 < nkt) {
                const int kn = k0 + 64;
                unsigned* Kd = Ks + (buf^1)*KVT;
                unsigned* Vd = Vs + (buf^1)*KVT;
                #pragma unroll
                for (int i = 0; i < 2; i++) {
                    int idx = tid + i*256;
                    int rr = idx >> 3, seg = idx & 7;
                    cpa16(&Kd[rr*FS + seg*4], &Kb[(size_t)(kn+rr)*DH_ + seg*8]);
                    cpa16(&Vd[rr*FS + seg*4], &Vb[(size_t)(kn+rr)*DH_ + seg*8]);
                }
                cpa_commit();
            }

            const bool active = (k0 <= wrow_min + 15);
            if (active) {
                const unsigned* Kbuf = Ks + buf*KVT;
                const unsigned* Vbuf = Vs + buf*KVT;

                // ---- S = Q K^T, fp16 accumulators; K frags non-trans ldsm ----
                unsigned sh[8], sh8[8];
                #pragma unroll
                for (int j = 0; j < 8; j++) {
                    unsigned sc2[2] = {0u, 0u};
                    unsigned kA[4], kB[4];
                    unsigned base = (unsigned)__cvta_generic_to_shared(
                        Kbuf + (j*8 + (lane & 7))*FS + ((lane >> 3) & 3)*4);
                    ldsm4(kA[0], kA[1], kA[2], kA[3], base);
                    ldsm4(kB[0], kB[1], kB[2], kB[3], base + 64);
                    mmaf16h(sc2, aq[0][0], aq[0][1], aq[0][2], aq[0][3], kA[0], kA[1]);
                    mmaf16h(sc2, aq[1][0], aq[1][1], aq[1][2], aq[1][3], kA[2], kA[3]);
                    mmaf16h(sc2, aq[2][0], aq[2][1], aq[2][2], aq[2][3], kB[0], kB[1]);
                    mmaf16h(sc2, aq[3][0], aq[3][1], aq[3][2], aq[3][3], kB[2], kB[3]);
                    sh[j] = sc2[0]; sh8[j] = sc2[1];
                }
                // ---- causal mask ----
                if (k0 + 63 > wrow_min) {
                    #pragma unroll
                    for (int j = 0; j < 8; j++) {
                        int c0 = k0 + j*8 + 2*tig;
                        unsigned mk  = (c0 > row_r  ? 0xFC00u : 0u) | (c0+1 > row_r  ? 0xFC000000u : 0u);
                        unsigned mk8 = (c0 > row_r8 ? 0xFC00u : 0u) | (c0+1 > row_r8 ? 0xFC000000u : 0u);
                        sh[j]  = h2u(__hadd2(u2h(sh[j]),  u2h(mk)));
                        sh8[j] = h2u(__hadd2(u2h(sh8[j]), u2h(mk8)));
                    }
                }
                // ---- packed max ----
                __half2 mx2 = u2h(sh[0]), mx28 = u2h(sh8[0]);
                #pragma unroll
                for (int j = 1; j < 8; j++) {
                    mx2  = __hmax2(mx2,  u2h(sh[j]));
                    mx28 = __hmax2(mx28, u2h(sh8[j]));
                }
                float mx_r  = fmaxf(__low2float(mx2),  __high2float(mx2));
                float mx_r8 = fmaxf(__low2float(mx28), __high2float(mx28));
                mx_r  = fmaxf(mx_r,  __shfl_xor_sync(0xffffffffu, mx_r,  1));
                mx_r  = fmaxf(mx_r,  __shfl_xor_sync(0xffffffffu, mx_r,  2));
                mx_r8 = fmaxf(mx_r8, __shfl_xor_sync(0xffffffffu, mx_r8, 1));
                mx_r8 = fmaxf(mx_r8, __shfl_xor_sync(0xffffffffu, mx_r8, 2));
                float mn_r  = fmaxf(m_r,  mx_r);
                float mn_r8 = fmaxf(m_r8, mx_r8);
                float corr_r  = ex2f(m_r  - mn_r);
                float corr_r8 = ex2f(m_r8 - mn_r8);
                m_r = mn_r; m_r8 = mn_r8;
                __half2 m2r  = __float2half2_rn(m_r);
                __half2 m2r8 = __float2half2_rn(m_r8);

                // ---- p = ex2(s - m) packed -> PV A-fragments ----
                unsigned ap[4][4];
                #pragma unroll
                for (int j = 0; j < 8; j++) {
                    unsigned p  = ex2h2(h2u(__hsub2(u2h(sh[j]),  m2r )));
                    unsigned p8 = ex2h2(h2u(__hsub2(u2h(sh8[j]), m2r8)));
                    int c = j >> 1, hi = j & 1;
                    ap[c][hi*2    ] = p;
                    ap[c][hi*2 + 1] = p8;
                }

                // ---- rescale accumulators ----
                #pragma unroll
                for (int jd = 0; jd < 8; jd++) {
                    oc[jd][0] *= corr_r;  oc[jd][1] *= corr_r;
                    oc[jd][2] *= corr_r8; oc[jd][3] *= corr_r8;
                }
                cl0 *= corr_r; cl2 *= corr_r8;

                // ---- O += P V ; l += P 1 ----
                const int lrow = lane & 15;
                const int lcol8 = (lane & 16) ? 8 : 0;
                #pragma unroll
                for (int c = 0; c < 4; c++) {
                    #pragma unroll
                    for (int jd2 = 0; jd2 < 4; jd2++) {
                        unsigned addr = (unsigned)__cvta_generic_to_shared(
                            (const char*)(Vbuf + (c*16 + lrow)*FS + jd2*8) + lcol8*2);
                        unsigned r0, r1, r2, r3;
                        ldsm4t(r0, r1, r2, r3, addr);
                        mmaf16(oc[2*jd2    ], ap[c][0], ap[c][1], ap[c][2], ap[c][3], r0, r1);
                        mmaf16(oc[2*jd2 + 1], ap[c][0], ap[c][1], ap[c][2], ap[c][3], r2, r3);
                    }
                    unsigned laddr = (unsigned)__cvta_generic_to_shared(
                        Vbuf + (c*16 + lrow)*FS + 32);
                    unsigned l0, l1;
                    ldsm2t(l0, l1, laddr);
                    float clf[4] = {cl0, cl1, cl2, cl3};
                    mmaf16(clf, ap[c][0], ap[c][1], ap[c][2], ap[c][3], l0, l1);
                    cl0 = clf[0]; cl1 = clf[1]; cl2 = clf[2]; cl3 = clf[3];
                }
            }
        }

        // ---- epilogue: l in col 64 (tig==0 lanes); broadcast in quad ----
        float l_r  = __shfl_sync(0xffffffffu, cl0, lane & ~3);
        float l_r8 = __shfl_sync(0xffffffffu, cl2, lane & ~3);
        float inv_r = 1.0f / l_r, inv_r8 = 1.0f / l_r8;
        __half* o0 = g_attn + ((size_t)(b*N_ + row_r )*INNER + h*DH_);
        __half* o1 = g_attn + ((size_t)(b*N_ + row_r8)*INNER + h*DH_);
        #pragma unroll
        for (int jd = 0; jd < 8; jd++) {
            int c = jd*8 + 2*tig;
            *(__half2*)&o0[c] = __floats2half2_rn(oc[jd][0]*inv_r,  oc[jd][1]*inv_r );
            *(__half2*)&o1[c] = __floats2half2_rn(oc[jd][2]*inv_r8, oc[jd][3]*inv_r8);
        }
    }
}

// =====================================================================
extern "C" void kernel_launch(void* const* d_in, const int* in_sizes, int n_in,
                              void* d_out, int out_size)
{
    const float* x   = (const float*)d_in[0];
    const float* Wq  = (const float*)d_in[1];
    const float* Wkv = (const float*)d_in[2];
    const float* Wo  = (const float*)d_in[3];
    const float* bo  = (const float*)d_in[4];
    float* out = (float*)d_out;

    cudaFuncSetAttribute(qkv_f16_kernel,
                         cudaFuncAttributeMaxDynamicSharedMemorySize, GEMM_SMEM);
    cudaFuncSetAttribute(out_f16_kernel,
                         cudaFuncAttributeMaxDynamicSharedMemorySize, GEMM_SMEM);

    prepass_kernel<<<4096 + 1024, 256>>>(x, Wq, Wkv, Wo);
    qkv_f16_kernel<<<dim3(12, 64), 256, GEMM_SMEM>>>();
    flash_f16_kernel<<<dim3(16, B_*H_), 256>>>();
    out_f16_kernel<<<dim3(4, 64), 256, GEMM_SMEM>>>(bo, out);
}